// round 9
// baseline (speedup 1.0000x reference)
#include <cuda_runtime.h>
#include <cstdint>

// resRNN: x(256,1024,8), W1(521,512), b1(512), W2(512,1), b2(1)
// out = [output(256,1024,1) | implied_storage(256,1024,1)]
//
// 128 CTAs = 16 rowgroups x 8 colgroups (cluster(8) = rowgroup, used only for
// the init barrier). Per-step sync is flag-based and per-source: warp w of CTA
// cg consumes source (cg+w)&7's transposed hx tile, gated by that source's
// flag. Own source needs no wait. No per-step cluster barrier.

#define TPB 256

static __device__ float g_hxT[2][16][8][64][16];  // [parity][rg][cg][col][row]
static __device__ float g_part[2][16][8][16];     // readout partials
static __device__ int   g_flag[16][8];            // last published step per CTA

// smem layout (float offsets)
#define OFF_W    0              // 544*64 = 34816
#define OFF_IT   34816          // 544*20 = 10880 (inpT[k][20])
#define OFF_RED  45696          // 8*16*68 = 8704
#define OFF_B1   54400          // 64
#define OFF_W2   54464          // 64
#define OFF_S    54528          // 16
#define OFF_SP   54544          // 8*16 = 128 (per-source readout partials)
#define SMEM_FLOATS 54672
#define SMEM_BYTES (SMEM_FLOATS * 4)

__device__ __forceinline__ float tanh_ex(float v) {
    float e = __expf(2.0f * v);
    return 1.0f - __fdividef(2.0f, e + 1.0f);
}
__device__ __forceinline__ int ld_acq(const int* p) {
    int v;
    asm volatile("ld.acquire.gpu.global.s32 %0, [%1];" : "=r"(v) : "l"(p) : "memory");
    return v;
}
__device__ __forceinline__ void st_rel(int* p, int v) {
    asm volatile("st.release.gpu.global.s32 [%0], %1;" :: "l"(p), "r"(v) : "memory");
}

__global__ void __cluster_dims__(8, 1, 1) __launch_bounds__(256, 1)
resRNN_kernel(const float* __restrict__ x, const float* __restrict__ W1,
              const float* __restrict__ b1, const float* __restrict__ W2,
              const float* __restrict__ b2, float* __restrict__ dout)
{
    extern __shared__ float sm[];
    float* Wsm   = sm + OFF_W;
    float* inpT  = sm + OFF_IT;
    float* red   = sm + OFF_RED;
    float* b1s   = sm + OFF_B1;
    float* w2s   = sm + OFF_W2;
    float* s_sm  = sm + OFF_S;
    float* spart = sm + OFF_SP;

    const int tid  = threadIdx.x;
    const int warp = tid >> 5;
    const int lane = tid & 31;
    const int cg   = blockIdx.x;
    const int rg   = blockIdx.y;
    const int row0 = rg * 16;
    const int src  = (cg + warp) & 7;          // source CTA this warp consumes

    // ---- init ----
    for (int i = tid; i < 544 * 16; i += TPB) {
        int k = i >> 4, f4 = i & 15;
        float4 v = make_float4(0.f, 0.f, 0.f, 0.f);
        if (k < 521) v = *(const float4*)&W1[k * 512 + cg * 64 + f4 * 4];
        *(float4*)&Wsm[k * 64 + f4 * 4] = v;
    }
    for (int i = tid; i < 544 * 20; i += TPB) inpT[i] = 0.f;
    if (tid < 64) { b1s[tid] = b1[cg * 64 + tid]; w2s[tid] = W2[cg * 64 + tid]; }
    if (tid < 16) s_sm[tid] = 0.f;
    if (tid == 0) g_flag[rg][cg] = -1;        // replay-safe reset
    const float b2v = b2[0];
    float* outp = dout;
    float* stop = dout + 256 * 1024;

    // xpre: lane<16 holds x_t[row=lane][comp=warp]; start with x_0
    float xpre = 0.f;
    if (lane < 16) xpre = x[(row0 + lane) * 8192 + warp];

    __syncthreads();
    __threadfence();
    asm volatile("barrier.cluster.arrive.aligned;" ::: "memory");
    asm volatile("barrier.cluster.wait.aligned;" ::: "memory");

    for (int t = 0; t < 1024; ++t) {
        const int pw = t & 1;       // publish parity (step t)
        const int pr = pw ^ 1;      // parity of step t-1 data

        // ---- stage x_t row 'warp'; prefetch x_{t+1} ----
        if (lane < 16) inpT[warp * 20 + lane] = xpre;
        if (t < 1023 && lane < 16)
            xpre = x[(row0 + lane) * 8192 + (t + 1) * 8 + warp];

        // ---- fetch this warp's source tile + readout partial (step t-1) ----
        if (t > 0) {
            if (src != cg) {
                const int* fp = &g_flag[rg][src];
                while (ld_acq(fp) < t - 1) {}
            }
            float part = 0.f;
            if (lane < 16) part = __ldcg(&g_part[pr][rg][src][lane]);
            if (src != cg) {
                // lane owns cols 2*lane, 2*lane+1 -> 32 contiguous floats
                const float4* tp = (const float4*)&g_hxT[pr][rg][src][2 * lane][0];
                float4 q0 = __ldcg((const float4*)tp + 0), q1 = __ldcg((const float4*)tp + 1);
                float4 q2 = __ldcg((const float4*)tp + 2), q3 = __ldcg((const float4*)tp + 3);
                float4 q4 = __ldcg((const float4*)tp + 4), q5 = __ldcg((const float4*)tp + 5);
                float4 q6 = __ldcg((const float4*)tp + 6), q7 = __ldcg((const float4*)tp + 7);
                float* d0 = &inpT[(9 + 64 * src + 2 * lane) * 20];
                float* d1 = d0 + 20;
                ((float4*)d0)[0] = q0; ((float4*)d0)[1] = q1;
                ((float4*)d0)[2] = q2; ((float4*)d0)[3] = q3;
                ((float4*)d1)[0] = q4; ((float4*)d1)[1] = q5;
                ((float4*)d1)[2] = q6; ((float4*)d1)[3] = q7;
            }
            if (lane < 16) spart[src * 16 + lane] = part;
        } else {
            if (lane < 16) spart[src * 16 + lane] = 0.f;
        }
        __syncwarp();

        // ---- GEMM: 64 source rows + 1 x row; cols (2*lane, 2*lane+1), 16 batch rows
        unsigned long long acc0[8], acc1[8];
        #pragma unroll
        for (int i = 0; i < 8; ++i) { acc0[i] = 0ull; acc1[i] = 0ull; }
        {
            const float* Ip = inpT + (9 + 64 * src) * 20;
            const float* Wp = Wsm + (9 + 64 * src) * 64 + 2 * lane;
            #pragma unroll 4
            for (int kk = 0; kk < 64; ++kk) {
                unsigned long long pr_[8];
                #pragma unroll
                for (int j = 0; j < 4; ++j) {
                    ulonglong2 q = *(const ulonglong2*)(Ip + kk * 20 + 4 * j);
                    pr_[2 * j] = q.x; pr_[2 * j + 1] = q.y;
                }
                float2 wv = *(const float2*)(Wp + kk * 64);
                unsigned long long w00, w11;
                asm("mov.b64 %0, {%1, %1};" : "=l"(w00) : "f"(wv.x));
                asm("mov.b64 %0, {%1, %1};" : "=l"(w11) : "f"(wv.y));
                #pragma unroll
                for (int p = 0; p < 8; ++p) {
                    asm("fma.rn.f32x2 %0, %1, %2, %0;" : "+l"(acc0[p]) : "l"(pr_[p]), "l"(w00));
                    asm("fma.rn.f32x2 %0, %1, %2, %0;" : "+l"(acc1[p]) : "l"(pr_[p]), "l"(w11));
                }
            }
            // x row (k index = warp)
            const float* Ipx = inpT + warp * 20;
            unsigned long long pr_[8];
            #pragma unroll
            for (int j = 0; j < 4; ++j) {
                ulonglong2 q = *(const ulonglong2*)(Ipx + 4 * j);
                pr_[2 * j] = q.x; pr_[2 * j + 1] = q.y;
            }
            float2 wv = *(const float2*)(Wsm + warp * 64 + 2 * lane);
            unsigned long long w00, w11;
            asm("mov.b64 %0, {%1, %1};" : "=l"(w00) : "f"(wv.x));
            asm("mov.b64 %0, {%1, %1};" : "=l"(w11) : "f"(wv.y));
            #pragma unroll
            for (int p = 0; p < 8; ++p) {
                asm("fma.rn.f32x2 %0, %1, %2, %0;" : "+l"(acc0[p]) : "l"(pr_[p]), "l"(w00));
                asm("fma.rn.f32x2 %0, %1, %2, %0;" : "+l"(acc1[p]) : "l"(pr_[p]), "l"(w11));
            }
        }

        // ---- spill k-partials ----
        #pragma unroll
        for (int p = 0; p < 8; ++p) {
            float2 a0 = *(float2*)&acc0[p];
            float2 a1 = *(float2*)&acc1[p];
            *(float2*)&red[(warp * 16 + 2 * p)     * 68 + 2 * lane] = make_float2(a0.x, a1.x);
            *(float2*)&red[(warp * 16 + 2 * p + 1) * 68 + 2 * lane] = make_float2(a0.y, a1.y);
        }
        __syncthreads();

        // ---- reduce + mass balance + tanh + publish ----
        {
            int r = tid >> 4, c4 = (tid & 15) * 4;
            float4 v = make_float4(0.f, 0.f, 0.f, 0.f);
            #pragma unroll
            for (int w = 0; w < 8; ++w) {
                float4 p = *(const float4*)&red[(w * 16 + r) * 68 + c4];
                v.x += p.x; v.y += p.y; v.z += p.z; v.w += p.w;
            }
            // out_{t-1} and s_t (computed redundantly by the 16 threads of row r)
            float o = 0.f;
            if (t > 0) {
                o = b2v;
                #pragma unroll
                for (int j = 0; j < 8; ++j) o += spart[j * 16 + r];
            }
            float s = s_sm[r] + inpT[r] - o;     // inpT[r] = x_t[0][r]
            if ((tid & 15) == 0) {
                s_sm[r] = s;                      // lockstep: reads above precede
                if (cg == 0) {
                    if (t > 0) outp[(row0 + r) * 1024 + (t - 1)] = o;
                    stop[(row0 + r) * 1024 + t] = s;
                }
            }
            float4 w8 = *(const float4*)&Wsm[8 * 64 + c4];
            v.x += s * w8.x; v.y += s * w8.y; v.z += s * w8.z; v.w += s * w8.w;

            v.x = tanh_ex(v.x + b1s[c4 + 0]);
            v.y = tanh_ex(v.y + b1s[c4 + 1]);
            v.z = tanh_ex(v.z + b1s[c4 + 2]);
            v.w = tanh_ex(v.w + b1s[c4 + 3]);

            // own tile straight into own inpT (next step, warp 0 reads it)
            inpT[(9 + 64 * cg + c4 + 0) * 20 + r] = v.x;
            inpT[(9 + 64 * cg + c4 + 1) * 20 + r] = v.y;
            inpT[(9 + 64 * cg + c4 + 2) * 20 + r] = v.z;
            inpT[(9 + 64 * cg + c4 + 3) * 20 + r] = v.w;
            // publish transposed tile for peers
            float* hb = &g_hxT[pw][rg][cg][0][0];
            hb[(c4 + 0) * 16 + r] = v.x;
            hb[(c4 + 1) * 16 + r] = v.y;
            hb[(c4 + 2) * 16 + r] = v.z;
            hb[(c4 + 3) * 16 + r] = v.w;
            // readout partial
            float p = v.x * w2s[c4] + v.y * w2s[c4 + 1] + v.z * w2s[c4 + 2] + v.w * w2s[c4 + 3];
            #pragma unroll
            for (int off = 8; off > 0; off >>= 1)
                p += __shfl_xor_sync(0xffffffffu, p, off);
            if ((tid & 15) == 0) g_part[pw][rg][cg][r] = p;
        }
        __threadfence();
        __syncthreads();
        if (tid == 0) st_rel(&g_flag[rg][cg], t);
    }

    // ---- epilogue: out_{1023} ----
    if (cg == 0 && tid < 16) {
        #pragma unroll
        for (int j = 1; j < 8; ++j) {
            const int* fp = &g_flag[rg][j];
            while (ld_acq(fp) < 1023) {}
        }
        float o = b2v;
        #pragma unroll
        for (int g = 0; g < 8; ++g) o += __ldcg(&g_part[1][rg][g][tid]);
        outp[(row0 + tid) * 1024 + 1023] = o;
    }
}

extern "C" void kernel_launch(void* const* d_in, const int* in_sizes, int n_in,
                              void* d_out, int out_size) {
    const float* x  = (const float*)d_in[0];
    const float* W1 = (const float*)d_in[1];
    const float* b1 = (const float*)d_in[2];
    const float* W2 = (const float*)d_in[3];
    const float* b2 = (const float*)d_in[4];
    float* out = (float*)d_out;

    cudaFuncSetAttribute(resRNN_kernel, cudaFuncAttributeMaxDynamicSharedMemorySize, SMEM_BYTES);

    dim3 grid(8, 16, 1);
    dim3 block(TPB, 1, 1);
    resRNN_kernel<<<grid, block, SMEM_BYTES>>>(x, W1, b1, W2, b2, out);
}